// round 15
// baseline (speedup 1.0000x reference)
#include <cuda_runtime.h>
#include <cuda_fp16.h>
#include <math.h>
#include <stdint.h>

// Problem constants
#define Bq   4
#define Sq   2048
#define Dm   1024
#define Hh   16
#define HDm  64
#define DFm  4096
#define NTOK (Bq*Sq)   // 8192
#define QKV_SZ (NTOK*Dm)

// ---------------------------------------------------------------------------
// Scratch (module-load allocated)
// ---------------------------------------------------------------------------
__device__ float g_x2 [NTOK*Dm];
__device__ float g_bqkv[3*Dm];

__device__ __half g_a  [NTOK*Dm];      // LN output / attention output (fp16)
__device__ __half g_h  [NTOK*DFm];     // FFN hidden (fp16)

__device__ __half g_q [QKV_SZ];
__device__ __half g_k [QKV_SZ];
__device__ __half g_v [QKV_SZ];

__device__ __half g_wqkv[3*Dm*Dm];     // fused QKV weights, [3072, 1024] K-major
__device__ __half g_wo [Dm*Dm];
__device__ __half g_w1 [Dm*DFm];
__device__ __half g_w2 [Dm*DFm];

// ---------------------------------------------------------------------------
// PTX helpers
// ---------------------------------------------------------------------------
__device__ __forceinline__ uint32_t s2u(const void* p) {
    uint32_t a;
    asm("{ .reg .u64 t; cvta.to.shared.u64 t, %1; cvt.u32.u64 %0, t; }"
        : "=r"(a) : "l"(p));
    return a;
}
__device__ __forceinline__ void cpa16(uint32_t d, const void* s) {
    asm volatile("cp.async.cg.shared.global [%0], [%1], 16;"
                 :: "r"(d), "l"(s) : "memory");
}
__device__ __forceinline__ void cpa_commit() {
    asm volatile("cp.async.commit_group;" ::: "memory");
}
template<int NN> __device__ __forceinline__ void cpa_wait() {
    asm volatile("cp.async.wait_group %0;" :: "n"(NN) : "memory");
}
__device__ __forceinline__ void ldsm4(uint32_t* r, uint32_t a) {
    asm volatile("ldmatrix.sync.aligned.m8n8.x4.shared.b16 {%0,%1,%2,%3}, [%4];"
                 : "=r"(r[0]), "=r"(r[1]), "=r"(r[2]), "=r"(r[3]) : "r"(a));
}
__device__ __forceinline__ void ldsm4t(uint32_t* r, uint32_t a) {
    asm volatile("ldmatrix.sync.aligned.m8n8.x4.trans.shared.b16 {%0,%1,%2,%3}, [%4];"
                 : "=r"(r[0]), "=r"(r[1]), "=r"(r[2]), "=r"(r[3]) : "r"(a));
}
__device__ __forceinline__ void mma_f16(float* d, const uint32_t* a, const uint32_t* b) {
    asm volatile(
        "mma.sync.aligned.m16n8k16.row.col.f32.f16.f16.f32 "
        "{%0,%1,%2,%3}, {%4,%5,%6,%7}, {%8,%9}, {%0,%1,%2,%3};"
        : "+f"(d[0]), "+f"(d[1]), "+f"(d[2]), "+f"(d[3])
        : "r"(a[0]), "r"(a[1]), "r"(a[2]), "r"(a[3]), "r"(b[0]), "r"(b[1]));
}

__device__ __forceinline__ uint32_t pack_h2(float x, float y) {
    __half2 h = __floats2half2_rn(x, y);
    return *(uint32_t*)&h;
}

#define SWZ(x) ((x) ^ (((x) >> 3) & 0x70))

// ---------------------------------------------------------------------------
// LayerNorm: one block per row, emits fp16
// ---------------------------------------------------------------------------
__global__ __launch_bounds__(256)
void ln_kernel(const float* __restrict__ X, const float* __restrict__ G,
               const float* __restrict__ Bt, __half* __restrict__ Y)
{
    __shared__ float ss[8], sq[8];
    const int r = blockIdx.x, tid = threadIdx.x;
    const float* xr = X + (size_t)r * Dm;
    float4 v = *(const float4*)(xr + tid * 4);
    float s = v.x + v.y + v.z + v.w;
    float q = v.x*v.x + v.y*v.y + v.z*v.z + v.w*v.w;
#pragma unroll
    for (int off = 16; off >= 1; off >>= 1) {
        s += __shfl_xor_sync(0xffffffffu, s, off);
        q += __shfl_xor_sync(0xffffffffu, q, off);
    }
    if ((tid & 31) == 0) { ss[tid >> 5] = s; sq[tid >> 5] = q; }
    __syncthreads();
    float ts = 0.f, tq = 0.f;
#pragma unroll
    for (int w = 0; w < 8; w++) { ts += ss[w]; tq += sq[w]; }
    const float mu   = ts * (1.0f / Dm);
    const float var  = tq * (1.0f / Dm) - mu * mu;
    const float rstd = rsqrtf(var + 1e-5f);
    float4 g4 = *(const float4*)(G  + tid * 4);
    float4 b4 = *(const float4*)(Bt + tid * 4);
    uint2 o;
    o.x = pack_h2((v.x - mu) * rstd * g4.x + b4.x, (v.y - mu) * rstd * g4.y + b4.y);
    o.y = pack_h2((v.z - mu) * rstd * g4.z + b4.z, (v.w - mu) * rstd * g4.w + b4.w);
    *(uint2*)(Y + (size_t)r * Dm + tid * 4) = o;
}

// ---------------------------------------------------------------------------
// Combined weight convert+transpose for ALL weights + QKV bias concat.
// ---------------------------------------------------------------------------
__global__ __launch_bounds__(256)
void wconv_all(const float* __restrict__ Wq, const float* __restrict__ Wk,
               const float* __restrict__ Wv, const float* __restrict__ Wo,
               const float* __restrict__ W1, const float* __restrict__ W2,
               const float* __restrict__ bq, const float* __restrict__ bk,
               const float* __restrict__ bv,
               __half* __restrict__ wqkv, __half* __restrict__ wo,
               __half* __restrict__ w1, __half* __restrict__ w2,
               float* __restrict__ bqkv)
{
    const int id = blockIdx.x;
    const int tx = threadIdx.x, ty = threadIdx.y;
    if (id >= 12288) {
        const int w = id - 12288;
        const float* src = (w == 0) ? bq : (w == 1) ? bk : bv;
        const int t = ty * 32 + tx;
#pragma unroll
        for (int i = 0; i < 4; i++)
            bqkv[w * Dm + t + i * 256] = src[t + i * 256];
        return;
    }
    const float* W; __half* T; int K, N, tile0;
    if      (id < 1024) { W = Wq; T = wqkv;            K = Dm;  N = Dm;  tile0 = 0; }
    else if (id < 2048) { W = Wk; T = wqkv + Dm*Dm;    K = Dm;  N = Dm;  tile0 = 1024; }
    else if (id < 3072) { W = Wv; T = wqkv + 2*Dm*Dm;  K = Dm;  N = Dm;  tile0 = 2048; }
    else if (id < 4096) { W = Wo; T = wo;              K = Dm;  N = Dm;  tile0 = 3072; }
    else if (id < 8192) { W = W1; T = w1;              K = Dm;  N = DFm; tile0 = 4096; }
    else                { W = W2; T = w2;              K = DFm; N = Dm;  tile0 = 8192; }
    const int lid = id - tile0;
    const int ntx = N >> 5;
    const int n0 = (lid % ntx) * 32, k0 = (lid / ntx) * 32;

    __shared__ float t[32][33];
#pragma unroll
    for (int i = 0; i < 4; i++)
        t[ty + i*8][tx] = W[(size_t)(k0 + ty + i*8) * N + n0 + tx];
    __syncthreads();
#pragma unroll
    for (int i = 0; i < 4; i++) {
        const int r = ty + i*8;
        T[(size_t)(n0 + r) * K + k0 + tx] = __float2half(t[tx][r]);
    }
}

// ---------------------------------------------------------------------------
// HMMA fp16 single-product GEMM (unchanged from R13/R14)
// ---------------------------------------------------------------------------
#define TMq 128
#define TNq 128
#define TILE_B   16384
#define STG_BYTES (2*TILE_B)         // 32768
#define GEMM_SMEM (3*STG_BYTES)      // 98304
#define OFF_BH (TILE_B)

__device__ __forceinline__ void load_stage(
    uint32_t st, const __half* __restrict__ A, const __half* __restrict__ Bh,
    int m0, int n0, int kc, int K, int tid)
{
#pragma unroll
    for (int j = 0; j < 4; j++) {
        const int i = tid + j * 256;
        const int r = i >> 3, c = i & 7;
        const uint32_t off = SWZ((uint32_t)(r * 128 + c * 16));
        cpa16(st + off,          A  + (size_t)(m0 + r) * K + kc + c * 8);
        cpa16(st + OFF_BH + off, Bh + (size_t)(n0 + r) * K + kc + c * 8);
    }
}

template<int MODE>
__global__ __launch_bounds__(256, 2)
void gemm_hmma(const __half* __restrict__ A, const __half* __restrict__ Bh,
               const float* __restrict__ bias, const float* __restrict__ res,
               float* __restrict__ Cf, __half* __restrict__ C16,
               __half* __restrict__ Ck, __half* __restrict__ Cv,
               int N, int K)
{
    extern __shared__ __align__(1024) char smem[];
    const uint32_t sb = s2u(smem);
    const int tid = threadIdx.x, lane = tid & 31, warp = tid >> 5;
    const int wm = warp >> 2, wn = warp & 3;
    const int m0 = blockIdx.y * TMq, n0 = blockIdx.x * TNq;

    float acc[4][4][4];
#pragma unroll
    for (int a = 0; a < 4; a++)
#pragma unroll
        for (int b = 0; b < 4; b++)
#pragma unroll
            for (int c = 0; c < 4; c++) acc[a][b][c] = 0.f;

    uint32_t rowA[4], rowB4[2];
#pragma unroll
    for (int mf = 0; mf < 4; mf++)
        rowA[mf] = (uint32_t)((wm*64 + mf*16 + (lane & 15)) * 128 + (lane >> 4) * 16);
#pragma unroll
    for (int nfp = 0; nfp < 2; nfp++)
        rowB4[nfp] = (uint32_t)((wn*32 + nfp*16 + ((lane >> 4) << 3) + (lane & 7)) * 128
                                + ((lane >> 3) & 1) * 16);

    const int NC = K >> 6;
    load_stage(sb,             A, Bh, m0, n0, 0,  K, tid); cpa_commit();
    load_stage(sb + STG_BYTES, A, Bh, m0, n0, 64, K, tid); cpa_commit();

    for (int c = 0; c < NC; c++) {
        if (c + 1 < NC) cpa_wait<1>(); else cpa_wait<0>();
        __syncthreads();
        if (c + 2 < NC) {
            load_stage(sb + ((c + 2) % 3) * STG_BYTES, A, Bh, m0, n0, (c + 2) * 64, K, tid);
            cpa_commit();
        }
        const uint32_t stA = sb + (c % 3) * STG_BYTES;
#pragma unroll
        for (int ks = 0; ks < 4; ks++) {
            const uint32_t ko = ks * 32;
            uint32_t ah[4][4], bh[2][4];
#pragma unroll
            for (int mf = 0; mf < 4; mf++)
                ldsm4(ah[mf], stA + SWZ(rowA[mf] + ko));
#pragma unroll
            for (int nfp = 0; nfp < 2; nfp++)
                ldsm4(bh[nfp], stA + OFF_BH + SWZ(rowB4[nfp] + ko));
#pragma unroll
            for (int mf = 0; mf < 4; mf++) {
                mma_f16(acc[mf][0], ah[mf], &bh[0][0]);
                mma_f16(acc[mf][1], ah[mf], &bh[0][2]);
                mma_f16(acc[mf][2], ah[mf], &bh[1][0]);
                mma_f16(acc[mf][3], ah[mf], &bh[1][2]);
            }
        }
    }

    const int qr = lane >> 2, qc = (lane & 3) * 2;
    __half* Oh = nullptr;
    float qsc = 1.0f;
    if (MODE == 3) {
        const int which = n0 >> 10;
        Oh = (which == 0) ? C16 : (which == 1) ? Ck : Cv;
        if (which == 0) qsc = 0.125f * 1.44269504088896f;  // fold scale*log2e into Q
    }
#pragma unroll
    for (int mf = 0; mf < 4; mf++) {
#pragma unroll
        for (int nf = 0; nf < 4; nf++) {
            const int row = m0 + wm*64 + mf*16 + qr;
            const int col = n0 + wn*32 + nf*8 + qc;
            float2 bv = *(const float2*)(bias + col);
            float x0 = acc[mf][nf][0] + bv.x, x1 = acc[mf][nf][1] + bv.y;
            float y0 = acc[mf][nf][2] + bv.x, y1 = acc[mf][nf][3] + bv.y;
            if (MODE == 1) {
                x0 *= normcdff(x0); x1 *= normcdff(x1);
                y0 *= normcdff(y0); y1 *= normcdff(y1);
                const size_t o0 = (size_t)row * N + col;
                const size_t o1 = (size_t)(row + 8) * N + col;
                *(uint32_t*)(C16 + o0) = pack_h2(x0, x1);
                *(uint32_t*)(C16 + o1) = pack_h2(y0, y1);
            } else if (MODE == 2) {
                const size_t o0 = (size_t)row * N + col;
                const size_t o1 = (size_t)(row + 8) * N + col;
                float2 r0 = *(const float2*)(res + o0);
                float2 r1 = *(const float2*)(res + o1);
                *(float2*)(Cf + o0) = make_float2(x0 + r0.x, x1 + r0.y);
                *(float2*)(Cf + o1) = make_float2(y0 + r1.x, y1 + r1.y);
            } else {
                const int coll = col & 1023;
                const int h = coll >> 6, hd = coll & 63;
                const int b0r = row >> 11, s0 = row & 2047;
                const int b1r = (row + 8) >> 11, s1 = (row + 8) & 2047;
                const size_t o0 = ((size_t)(b0r * Hh + h) * Sq + s0) * HDm + hd;
                const size_t o1 = ((size_t)(b1r * Hh + h) * Sq + s1) * HDm + hd;
                *(uint32_t*)(Oh + o0) = pack_h2(x0 * qsc, x1 * qsc);
                *(uint32_t*)(Oh + o1) = pack_h2(y0 * qsc, y1 * qsc);
            }
        }
    }
}

// ---------------------------------------------------------------------------
// HMMA flash attention, PING-PONG warp groups:
// 8 warps/CTA, 2 CTAs/SM. Warps 0-3 (A) own Q rows 0-63; warps 4-7 (B) own
// rows 64-127. A runs [QK(c); softmax(c); PV(c)]; B runs [softmax(c-1);
// PV(c-1); QK(c)] carrying its score accumulators across iterations -> B's
// MMAs fill A's softmax window and vice versa (anti-phased tensor/MUFU).
// KV ring = 4 stages (B reads tile c-1 while c+2 streams in).
// Scores in log2 domain (Q pre-scaled by 0.125*log2e); exp2f softmax.
// ---------------------------------------------------------------------------
#define ATT_QB   16384
#define ATT_KVB  8192
#define ATT_STG  (2*ATT_KVB)              // 16384
#define ATT_SMEM (ATT_QB + 4*ATT_STG)     // 81920 (x2 CTAs = 160KB/SM)

__device__ __forceinline__ void att_load_stage(
    uint32_t st, const __half* __restrict__ Kh, const __half* __restrict__ Vh,
    size_t tb, int kv0, int tid)
{
#pragma unroll
    for (int j = 0; j < 4; j++) {
        const int i = tid + j * 256;
        const int t = i >> 9;
        const int r = (i >> 3) & 63;
        const int c = i & 7;
        const __half* src = t ? Vh : Kh;
        cpa16(st + t * ATT_KVB + SWZ((uint32_t)(r * 128 + c * 16)),
              src + tb + (size_t)(kv0 + r) * HDm + c * 8);
    }
}

__device__ __forceinline__ void att_qk(float accs[8][4], const uint32_t qf[4][4],
                                       uint32_t stb, int lane)
{
#pragma unroll
    for (int nf = 0; nf < 8; nf++)
#pragma unroll
        for (int q4 = 0; q4 < 4; q4++) accs[nf][q4] = 0.f;
#pragma unroll
    for (int kf = 0; kf < 4; kf++) {
        uint32_t bhf[4][4];
#pragma unroll
        for (int nfp = 0; nfp < 4; nfp++) {
            const uint32_t row = (uint32_t)(16*nfp + ((lane >> 4) << 3) + (lane & 7));
            const uint32_t kb  = (uint32_t)(kf * 32 + ((lane >> 3) & 1) * 16);
            ldsm4(bhf[nfp], stb + SWZ(row * 128 + kb));
        }
#pragma unroll
        for (int nfp = 0; nfp < 4; nfp++) {
            mma_f16(accs[2*nfp],   qf[kf], &bhf[nfp][0]);
            mma_f16(accs[2*nfp+1], qf[kf], &bhf[nfp][2]);
        }
    }
}

__device__ __forceinline__ void att_softmax(float accs[8][4], float acco[8][4],
                                            float& m0v, float& m1v,
                                            float& l0v, float& l1v)
{
    float mx0 = -1e30f, mx1 = -1e30f;
#pragma unroll
    for (int nf = 0; nf < 8; nf++) {
        mx0 = fmaxf(mx0, fmaxf(accs[nf][0], accs[nf][1]));
        mx1 = fmaxf(mx1, fmaxf(accs[nf][2], accs[nf][3]));
    }
#pragma unroll
    for (int off = 1; off <= 2; off <<= 1) {
        mx0 = fmaxf(mx0, __shfl_xor_sync(0xffffffffu, mx0, off));
        mx1 = fmaxf(mx1, __shfl_xor_sync(0xffffffffu, mx1, off));
    }
    const float mn0 = fmaxf(m0v, mx0), mn1 = fmaxf(m1v, mx1);
    const float cr0 = exp2f(m0v - mn0), cr1 = exp2f(m1v - mn1);
    float sum0 = 0.f, sum1 = 0.f;
#pragma unroll
    for (int nf = 0; nf < 8; nf++) {
        float p0 = exp2f(accs[nf][0] - mn0);
        float p1 = exp2f(accs[nf][1] - mn0);
        float p2 = exp2f(accs[nf][2] - mn1);
        float p3 = exp2f(accs[nf][3] - mn1);
        accs[nf][0] = p0; accs[nf][1] = p1; accs[nf][2] = p2; accs[nf][3] = p3;
        sum0 += p0 + p1; sum1 += p2 + p3;
    }
#pragma unroll
    for (int off = 1; off <= 2; off <<= 1) {
        sum0 += __shfl_xor_sync(0xffffffffu, sum0, off);
        sum1 += __shfl_xor_sync(0xffffffffu, sum1, off);
    }
    l0v = l0v * cr0 + sum0;  m0v = mn0;
    l1v = l1v * cr1 + sum1;  m1v = mn1;
#pragma unroll
    for (int nf = 0; nf < 8; nf++) {
        acco[nf][0] *= cr0; acco[nf][1] *= cr0;
        acco[nf][2] *= cr1; acco[nf][3] *= cr1;
    }
}

__device__ __forceinline__ void att_pv(float acco[8][4], const float accs[8][4],
                                       uint32_t stb, int lane)
{
#pragma unroll
    for (int kf2 = 0; kf2 < 4; kf2++) {
        uint32_t aP[4];
        aP[0] = pack_h2(accs[2*kf2][0],   accs[2*kf2][1]);
        aP[1] = pack_h2(accs[2*kf2][2],   accs[2*kf2][3]);
        aP[2] = pack_h2(accs[2*kf2+1][0], accs[2*kf2+1][1]);
        aP[3] = pack_h2(accs[2*kf2+1][2], accs[2*kf2+1][3]);
#pragma unroll
        for (int nfp2 = 0; nfp2 < 4; nfp2++) {
            const uint32_t row  = (uint32_t)(16*kf2 + ((lane >> 3) & 1) * 8 + (lane & 7));
            const uint32_t colb = (uint32_t)(nfp2 * 32 + (lane >> 4) * 16);
            uint32_t vhf[4];
            ldsm4t(vhf, stb + ATT_KVB + SWZ(row * 128 + colb));
            mma_f16(acco[2*nfp2],   aP, &vhf[0]);
            mma_f16(acco[2*nfp2+1], aP, &vhf[2]);
        }
    }
}

__global__ __launch_bounds__(256, 2)
void attn_hmma(const __half* __restrict__ Qh_, const __half* __restrict__ Kh_,
               const __half* __restrict__ Vh_, __half* __restrict__ O)
{
    extern __shared__ __align__(1024) char smem[];
    const uint32_t sb = s2u(smem);
    const int tid = threadIdx.x, lane = tid & 31, warp = tid >> 5;
    const int bh = blockIdx.y;
    const int q0 = blockIdx.x * 128;
    const size_t tb = (size_t)bh * Sq * HDm;

    // prologue: KV tiles 0,1 + Q, fully drained
    att_load_stage(sb + ATT_QB,           Kh_, Vh_, tb, 0,  tid); cpa_commit();
    att_load_stage(sb + ATT_QB + ATT_STG, Kh_, Vh_, tb, 64, tid); cpa_commit();
#pragma unroll
    for (int j = 0; j < 4; j++) {
        const int i = tid + j * 256;
        const int r = i >> 3, c = i & 7;
        cpa16(sb + SWZ((uint32_t)(r * 128 + c * 16)),
              Qh_ + tb + (size_t)(q0 + r) * HDm + c * 8);
    }
    cpa_commit();
    cpa_wait<0>();
    __syncthreads();

    // Q fragments: warp w owns rows 16w (A: 0-63, B: 64-127)
    uint32_t qf[4][4];
    {
        const uint32_t qrow = (uint32_t)((16*warp + (lane & 15)) * 128 + (lane >> 4) * 16);
#pragma unroll
        for (int kf = 0; kf < 4; kf++)
            ldsm4(qf[kf], sb + SWZ(qrow + kf * 32));
    }

    float accs[8][4], acco[8][4];
#pragma unroll
    for (int nf = 0; nf < 8; nf++)
#pragma unroll
        for (int c = 0; c < 4; c++) acco[nf][c] = 0.f;
    float m0v = -1e30f, m1v = -1e30f, l0v = 0.f, l1v = 0.f;

    const bool grpA = (warp < 4);
    const int NT = Sq / 64;   // 32
    for (int c = 0; c < NT; c++) {
        if (c + 1 < NT) cpa_wait<1>(); else cpa_wait<0>();
        __syncthreads();     // tile c visible; buffer (c+2)&3 free (B done with c-2)
        if (c + 2 < NT) {
            att_load_stage(sb + ATT_QB + ((c + 2) & 3) * ATT_STG,
                           Kh_, Vh_, tb, (c + 2) * 64, tid);
            cpa_commit();
        }
        const uint32_t bufc = sb + ATT_QB + (c & 3) * ATT_STG;
        if (grpA) {
            att_qk(accs, qf, bufc, lane);
            att_softmax(accs, acco, m0v, m1v, l0v, l1v);
            att_pv(acco, accs, bufc, lane);
        } else {
            if (c > 0) {
                att_softmax(accs, acco, m0v, m1v, l0v, l1v);
                att_pv(acco, accs, sb + ATT_QB + ((c - 1) & 3) * ATT_STG, lane);
            }
            att_qk(accs, qf, bufc, lane);
        }
    }
    if (!grpA) {   // B's trailing tile NT-1
        att_softmax(accs, acco, m0v, m1v, l0v, l1v);
        att_pv(acco, accs, sb + ATT_QB + ((NT - 1) & 3) * ATT_STG, lane);
    }

    const float inv0 = 1.f / l0v, inv1 = 1.f / l1v;
    const int b = bh >> 4, h = bh & 15;
    const int s0 = q0 + warp * 16 + (lane >> 2), s1 = s0 + 8;
#pragma unroll
    for (int nf = 0; nf < 8; nf++) {
        const int col = h * HDm + nf * 8 + (lane & 3) * 2;
        const size_t o0 = (size_t)(b * Sq + s0) * Dm + col;
        const size_t o1 = (size_t)(b * Sq + s1) * Dm + col;
        *(uint32_t*)(O + o0) = pack_h2(acco[nf][0] * inv0, acco[nf][1] * inv0);
        *(uint32_t*)(O + o1) = pack_h2(acco[nf][2] * inv1, acco[nf][3] * inv1);
    }
}

// ---------------------------------------------------------------------------
extern "C" void kernel_launch(void* const* d_in, const int* in_sizes, int n_in,
                              void* d_out, int out_size)
{
    const float* x    = (const float*)d_in[0];
    const float* Wq   = (const float*)d_in[1];
    const float* bq   = (const float*)d_in[2];
    const float* Wk   = (const float*)d_in[3];
    const float* bk   = (const float*)d_in[4];
    const float* Wv   = (const float*)d_in[5];
    const float* bv   = (const float*)d_in[6];
    const float* Wo   = (const float*)d_in[7];
    const float* bo   = (const float*)d_in[8];
    const float* ln1g = (const float*)d_in[9];
    const float* ln1b = (const float*)d_in[10];
    const float* ln2g = (const float*)d_in[11];
    const float* ln2b = (const float*)d_in[12];
    const float* W1   = (const float*)d_in[13];
    const float* b1   = (const float*)d_in[14];
    const float* W2   = (const float*)d_in[15];
    const float* b2   = (const float*)d_in[16];
    float* out = (float*)d_out;

    float *x2, *bqkv;
    __half *a16, *h16, *q16, *k16, *v16;
    __half *wqkv, *wo, *w1, *w2;
    cudaGetSymbolAddress((void**)&x2,   g_x2);
    cudaGetSymbolAddress((void**)&bqkv, g_bqkv);
    cudaGetSymbolAddress((void**)&a16,  g_a);
    cudaGetSymbolAddress((void**)&h16,  g_h);
    cudaGetSymbolAddress((void**)&q16,  g_q);
    cudaGetSymbolAddress((void**)&k16,  g_k);
    cudaGetSymbolAddress((void**)&v16,  g_v);
    cudaGetSymbolAddress((void**)&wqkv, g_wqkv);
    cudaGetSymbolAddress((void**)&wo,   g_wo);
    cudaGetSymbolAddress((void**)&w1,   g_w1);
    cudaGetSymbolAddress((void**)&w2,   g_w2);

    cudaFuncSetAttribute(attn_hmma, cudaFuncAttributeMaxDynamicSharedMemorySize, ATT_SMEM);
    cudaFuncSetAttribute(gemm_hmma<1>, cudaFuncAttributeMaxDynamicSharedMemorySize, GEMM_SMEM);
    cudaFuncSetAttribute(gemm_hmma<2>, cudaFuncAttributeMaxDynamicSharedMemorySize, GEMM_SMEM);
    cudaFuncSetAttribute(gemm_hmma<3>, cudaFuncAttributeMaxDynamicSharedMemorySize, GEMM_SMEM);

    const dim3 blk(256);
    const dim3 wblk(32, 8);
    const dim3 gQKV(3*Dm / TNq, NTOK / TMq);  // (24, 64)
    const dim3 gP  (Dm   / TNq, NTOK / TMq);  // (8, 64)
    const dim3 gF1 (DFm  / TNq, NTOK / TMq);  // (32, 64)

    // 0) all weight converts + QKV bias concat in ONE launch
    wconv_all<<<12291, wblk>>>(Wq, Wk, Wv, Wo, W1, W2, bq, bk, bv,
                               wqkv, wo, w1, w2, bqkv);

    // 1) LN1 -> fp16
    ln_kernel<<<NTOK, blk>>>(x, ln1g, ln1b, a16);
    // 2) fused QKV projection -> fp16 scattered [B,H,S,64]; Q scaled 0.125*log2e
    gemm_hmma<3><<<gQKV, blk, GEMM_SMEM>>>(a16, wqkv, bqkv, nullptr, nullptr,
                                           q16, k16, v16, 3*Dm, Dm);
    // 3) attention (ping-pong warp groups, 2 CTAs/SM) -> fp16 [B,S,D]
    attn_hmma<<<dim3(Sq / 128, Bq * Hh), blk, ATT_SMEM>>>(q16, k16, v16, a16);
    // 4) output projection + residual -> x2 (f32)
    gemm_hmma<2><<<gP, blk, GEMM_SMEM>>>(a16, wo, bo, x, x2,
                                         nullptr, nullptr, nullptr, Dm, Dm);
    // 5) LN2 -> fp16
    ln_kernel<<<NTOK, blk>>>(x2, ln2g, ln2b, a16);
    // 6) FFN up + exact GELU -> fp16
    gemm_hmma<1><<<gF1, blk, GEMM_SMEM>>>(a16, w1, b1, nullptr, nullptr,
                                          h16, nullptr, nullptr, DFm, Dm);
    // 7) FFN down + residual -> out (f32)
    gemm_hmma<2><<<gP, blk, GEMM_SMEM>>>(h16, w2, b2, x2, out,
                                         nullptr, nullptr, nullptr, Dm, DFm);
}

// round 16
// speedup vs baseline: 1.0262x; 1.0262x over previous
#include <cuda_runtime.h>
#include <cuda_fp16.h>
#include <math.h>
#include <stdint.h>

// Problem constants
#define Bq   4
#define Sq   2048
#define Dm   1024
#define Hh   16
#define HDm  64
#define DFm  4096
#define NTOK (Bq*Sq)   // 8192
#define QKV_SZ (NTOK*Dm)

// ---------------------------------------------------------------------------
// Scratch (module-load allocated)
// ---------------------------------------------------------------------------
__device__ float g_x2 [NTOK*Dm];
__device__ float g_bqkv[3*Dm];

__device__ __half g_a  [NTOK*Dm];      // LN output / attention output (fp16)
__device__ __half g_h  [NTOK*DFm];     // FFN hidden (fp16)

__device__ __half g_q [QKV_SZ];
__device__ __half g_k [QKV_SZ];
__device__ __half g_v [QKV_SZ];

__device__ __half g_wqkv[3*Dm*Dm];     // fused QKV weights, [3072, 1024] K-major
__device__ __half g_wo [Dm*Dm];
__device__ __half g_w1 [Dm*DFm];
__device__ __half g_w2 [Dm*DFm];

// ---------------------------------------------------------------------------
// PTX helpers
// ---------------------------------------------------------------------------
__device__ __forceinline__ uint32_t s2u(const void* p) {
    uint32_t a;
    asm("{ .reg .u64 t; cvta.to.shared.u64 t, %1; cvt.u32.u64 %0, t; }"
        : "=r"(a) : "l"(p));
    return a;
}
__device__ __forceinline__ void cpa16(uint32_t d, const void* s) {
    asm volatile("cp.async.cg.shared.global [%0], [%1], 16;"
                 :: "r"(d), "l"(s) : "memory");
}
__device__ __forceinline__ void cpa_commit() {
    asm volatile("cp.async.commit_group;" ::: "memory");
}
template<int NN> __device__ __forceinline__ void cpa_wait() {
    asm volatile("cp.async.wait_group %0;" :: "n"(NN) : "memory");
}
__device__ __forceinline__ void ldsm4(uint32_t* r, uint32_t a) {
    asm volatile("ldmatrix.sync.aligned.m8n8.x4.shared.b16 {%0,%1,%2,%3}, [%4];"
                 : "=r"(r[0]), "=r"(r[1]), "=r"(r[2]), "=r"(r[3]) : "r"(a));
}
__device__ __forceinline__ void ldsm4t(uint32_t* r, uint32_t a) {
    asm volatile("ldmatrix.sync.aligned.m8n8.x4.trans.shared.b16 {%0,%1,%2,%3}, [%4];"
                 : "=r"(r[0]), "=r"(r[1]), "=r"(r[2]), "=r"(r[3]) : "r"(a));
}
__device__ __forceinline__ void mma_f16(float* d, const uint32_t* a, const uint32_t* b) {
    asm volatile(
        "mma.sync.aligned.m16n8k16.row.col.f32.f16.f16.f32 "
        "{%0,%1,%2,%3}, {%4,%5,%6,%7}, {%8,%9}, {%0,%1,%2,%3};"
        : "+f"(d[0]), "+f"(d[1]), "+f"(d[2]), "+f"(d[3])
        : "r"(a[0]), "r"(a[1]), "r"(a[2]), "r"(a[3]), "r"(b[0]), "r"(b[1]));
}

__device__ __forceinline__ uint32_t pack_h2(float x, float y) {
    __half2 h = __floats2half2_rn(x, y);
    return *(uint32_t*)&h;
}
// packed fp16x2 exp2 (MUFU, one issue per pair)
__device__ __forceinline__ uint32_t h2exp2(float x, float y) {
    __half2 d = __floats2half2_rn(x, y);
    uint32_t p;
    asm("ex2.approx.f16x2 %0, %1;" : "=r"(p) : "r"(*(uint32_t*)&d));
    return p;
}

#define SWZ(x) ((x) ^ (((x) >> 3) & 0x70))

// ---------------------------------------------------------------------------
// LayerNorm: one block per row, emits fp16
// ---------------------------------------------------------------------------
__global__ __launch_bounds__(256)
void ln_kernel(const float* __restrict__ X, const float* __restrict__ G,
               const float* __restrict__ Bt, __half* __restrict__ Y)
{
    __shared__ float ss[8], sq[8];
    const int r = blockIdx.x, tid = threadIdx.x;
    const float* xr = X + (size_t)r * Dm;
    float4 v = *(const float4*)(xr + tid * 4);
    float s = v.x + v.y + v.z + v.w;
    float q = v.x*v.x + v.y*v.y + v.z*v.z + v.w*v.w;
#pragma unroll
    for (int off = 16; off >= 1; off >>= 1) {
        s += __shfl_xor_sync(0xffffffffu, s, off);
        q += __shfl_xor_sync(0xffffffffu, q, off);
    }
    if ((tid & 31) == 0) { ss[tid >> 5] = s; sq[tid >> 5] = q; }
    __syncthreads();
    float ts = 0.f, tq = 0.f;
#pragma unroll
    for (int w = 0; w < 8; w++) { ts += ss[w]; tq += sq[w]; }
    const float mu   = ts * (1.0f / Dm);
    const float var  = tq * (1.0f / Dm) - mu * mu;
    const float rstd = rsqrtf(var + 1e-5f);
    float4 g4 = *(const float4*)(G  + tid * 4);
    float4 b4 = *(const float4*)(Bt + tid * 4);
    uint2 o;
    o.x = pack_h2((v.x - mu) * rstd * g4.x + b4.x, (v.y - mu) * rstd * g4.y + b4.y);
    o.y = pack_h2((v.z - mu) * rstd * g4.z + b4.z, (v.w - mu) * rstd * g4.w + b4.w);
    *(uint2*)(Y + (size_t)r * Dm + tid * 4) = o;
}

// ---------------------------------------------------------------------------
// Combined weight convert+transpose for ALL weights + QKV bias concat.
// ---------------------------------------------------------------------------
__global__ __launch_bounds__(256)
void wconv_all(const float* __restrict__ Wq, const float* __restrict__ Wk,
               const float* __restrict__ Wv, const float* __restrict__ Wo,
               const float* __restrict__ W1, const float* __restrict__ W2,
               const float* __restrict__ bq, const float* __restrict__ bk,
               const float* __restrict__ bv,
               __half* __restrict__ wqkv, __half* __restrict__ wo,
               __half* __restrict__ w1, __half* __restrict__ w2,
               float* __restrict__ bqkv)
{
    const int id = blockIdx.x;
    const int tx = threadIdx.x, ty = threadIdx.y;
    if (id >= 12288) {
        const int w = id - 12288;
        const float* src = (w == 0) ? bq : (w == 1) ? bk : bv;
        const int t = ty * 32 + tx;
#pragma unroll
        for (int i = 0; i < 4; i++)
            bqkv[w * Dm + t + i * 256] = src[t + i * 256];
        return;
    }
    const float* W; __half* T; int K, N, tile0;
    if      (id < 1024) { W = Wq; T = wqkv;            K = Dm;  N = Dm;  tile0 = 0; }
    else if (id < 2048) { W = Wk; T = wqkv + Dm*Dm;    K = Dm;  N = Dm;  tile0 = 1024; }
    else if (id < 3072) { W = Wv; T = wqkv + 2*Dm*Dm;  K = Dm;  N = Dm;  tile0 = 2048; }
    else if (id < 4096) { W = Wo; T = wo;              K = Dm;  N = Dm;  tile0 = 3072; }
    else if (id < 8192) { W = W1; T = w1;              K = Dm;  N = DFm; tile0 = 4096; }
    else                { W = W2; T = w2;              K = DFm; N = Dm;  tile0 = 8192; }
    const int lid = id - tile0;
    const int ntx = N >> 5;
    const int n0 = (lid % ntx) * 32, k0 = (lid / ntx) * 32;

    __shared__ float t[32][33];
#pragma unroll
    for (int i = 0; i < 4; i++)
        t[ty + i*8][tx] = W[(size_t)(k0 + ty + i*8) * N + n0 + tx];
    __syncthreads();
#pragma unroll
    for (int i = 0; i < 4; i++) {
        const int r = ty + i*8;
        T[(size_t)(n0 + r) * K + k0 + tx] = __float2half(t[tx][r]);
    }
}

// ---------------------------------------------------------------------------
// HMMA fp16 single-product GEMM, single-barrier multistage pipeline (R13)
// ---------------------------------------------------------------------------
#define TMq 128
#define TNq 128
#define TILE_B   16384
#define STG_BYTES (2*TILE_B)         // 32768
#define GEMM_SMEM (3*STG_BYTES)      // 98304
#define OFF_BH (TILE_B)

__device__ __forceinline__ void load_stage(
    uint32_t st, const __half* __restrict__ A, const __half* __restrict__ Bh,
    int m0, int n0, int kc, int K, int tid)
{
#pragma unroll
    for (int j = 0; j < 4; j++) {
        const int i = tid + j * 256;
        const int r = i >> 3, c = i & 7;
        const uint32_t off = SWZ((uint32_t)(r * 128 + c * 16));
        cpa16(st + off,          A  + (size_t)(m0 + r) * K + kc + c * 8);
        cpa16(st + OFF_BH + off, Bh + (size_t)(n0 + r) * K + kc + c * 8);
    }
}

template<int MODE>
__global__ __launch_bounds__(256, 2)
void gemm_hmma(const __half* __restrict__ A, const __half* __restrict__ Bh,
               const float* __restrict__ bias, const float* __restrict__ res,
               float* __restrict__ Cf, __half* __restrict__ C16,
               __half* __restrict__ Ck, __half* __restrict__ Cv,
               int N, int K)
{
    extern __shared__ __align__(1024) char smem[];
    const uint32_t sb = s2u(smem);
    const int tid = threadIdx.x, lane = tid & 31, warp = tid >> 5;
    const int wm = warp >> 2, wn = warp & 3;
    const int m0 = blockIdx.y * TMq, n0 = blockIdx.x * TNq;

    float acc[4][4][4];
#pragma unroll
    for (int a = 0; a < 4; a++)
#pragma unroll
        for (int b = 0; b < 4; b++)
#pragma unroll
            for (int c = 0; c < 4; c++) acc[a][b][c] = 0.f;

    uint32_t rowA[4], rowB4[2];
#pragma unroll
    for (int mf = 0; mf < 4; mf++)
        rowA[mf] = (uint32_t)((wm*64 + mf*16 + (lane & 15)) * 128 + (lane >> 4) * 16);
#pragma unroll
    for (int nfp = 0; nfp < 2; nfp++)
        rowB4[nfp] = (uint32_t)((wn*32 + nfp*16 + ((lane >> 4) << 3) + (lane & 7)) * 128
                                + ((lane >> 3) & 1) * 16);

    const int NC = K >> 6;
    load_stage(sb,             A, Bh, m0, n0, 0,  K, tid); cpa_commit();
    load_stage(sb + STG_BYTES, A, Bh, m0, n0, 64, K, tid); cpa_commit();

    for (int c = 0; c < NC; c++) {
        if (c + 1 < NC) cpa_wait<1>(); else cpa_wait<0>();
        __syncthreads();
        if (c + 2 < NC) {
            load_stage(sb + ((c + 2) % 3) * STG_BYTES, A, Bh, m0, n0, (c + 2) * 64, K, tid);
            cpa_commit();
        }
        const uint32_t stA = sb + (c % 3) * STG_BYTES;
#pragma unroll
        for (int ks = 0; ks < 4; ks++) {
            const uint32_t ko = ks * 32;
            uint32_t ah[4][4], bh[2][4];
#pragma unroll
            for (int mf = 0; mf < 4; mf++)
                ldsm4(ah[mf], stA + SWZ(rowA[mf] + ko));
#pragma unroll
            for (int nfp = 0; nfp < 2; nfp++)
                ldsm4(bh[nfp], stA + OFF_BH + SWZ(rowB4[nfp] + ko));
#pragma unroll
            for (int mf = 0; mf < 4; mf++) {
                mma_f16(acc[mf][0], ah[mf], &bh[0][0]);
                mma_f16(acc[mf][1], ah[mf], &bh[0][2]);
                mma_f16(acc[mf][2], ah[mf], &bh[1][0]);
                mma_f16(acc[mf][3], ah[mf], &bh[1][2]);
            }
        }
    }

    const int qr = lane >> 2, qc = (lane & 3) * 2;
    __half* Oh = nullptr;
    float qsc = 1.0f;
    if (MODE == 3) {
        const int which = n0 >> 10;
        Oh = (which == 0) ? C16 : (which == 1) ? Ck : Cv;
        if (which == 0) qsc = 0.125f * 1.44269504088896f;  // fold scale*log2e into Q
    }
#pragma unroll
    for (int mf = 0; mf < 4; mf++) {
#pragma unroll
        for (int nf = 0; nf < 4; nf++) {
            const int row = m0 + wm*64 + mf*16 + qr;
            const int col = n0 + wn*32 + nf*8 + qc;
            float2 bv = *(const float2*)(bias + col);
            float x0 = acc[mf][nf][0] + bv.x, x1 = acc[mf][nf][1] + bv.y;
            float y0 = acc[mf][nf][2] + bv.x, y1 = acc[mf][nf][3] + bv.y;
            if (MODE == 1) {
                x0 *= normcdff(x0); x1 *= normcdff(x1);
                y0 *= normcdff(y0); y1 *= normcdff(y1);
                const size_t o0 = (size_t)row * N + col;
                const size_t o1 = (size_t)(row + 8) * N + col;
                *(uint32_t*)(C16 + o0) = pack_h2(x0, x1);
                *(uint32_t*)(C16 + o1) = pack_h2(y0, y1);
            } else if (MODE == 2) {
                const size_t o0 = (size_t)row * N + col;
                const size_t o1 = (size_t)(row + 8) * N + col;
                float2 r0 = *(const float2*)(res + o0);
                float2 r1 = *(const float2*)(res + o1);
                *(float2*)(Cf + o0) = make_float2(x0 + r0.x, x1 + r0.y);
                *(float2*)(Cf + o1) = make_float2(y0 + r1.x, y1 + r1.y);
            } else {
                const int coll = col & 1023;
                const int h = coll >> 6, hd = coll & 63;
                const int b0r = row >> 11, s0 = row & 2047;
                const int b1r = (row + 8) >> 11, s1 = (row + 8) & 2047;
                const size_t o0 = ((size_t)(b0r * Hh + h) * Sq + s0) * HDm + hd;
                const size_t o1 = ((size_t)(b1r * Hh + h) * Sq + s1) * HDm + hd;
                *(uint32_t*)(Oh + o0) = pack_h2(x0 * qsc, x1 * qsc);
                *(uint32_t*)(Oh + o1) = pack_h2(y0 * qsc, y1 * qsc);
            }
        }
    }
}

// ---------------------------------------------------------------------------
// HMMA flash attention (R13 shape: 16q/warp, 2 CTAs/SM, single-barrier ring).
// Softmax exp via ex2.approx.f16x2: one MUFU per score PAIR, emitting packed
// fp16 P that feeds the PV MMA directly (no separate pack step).
// Scores in log2 domain (Q pre-scaled by 0.125*log2e).
// ---------------------------------------------------------------------------
#define ATT_QB   16384
#define ATT_KVB  8192
#define ATT_STG  (2*ATT_KVB)              // 16384
#define ATT_SMEM (ATT_QB + 3*ATT_STG)     // 65536

__device__ __forceinline__ void att_load_stage(
    uint32_t st, const __half* __restrict__ Kh, const __half* __restrict__ Vh,
    size_t tb, int kv0, int tid)
{
#pragma unroll
    for (int j = 0; j < 4; j++) {
        const int i = tid + j * 256;
        const int t = i >> 9;
        const int r = (i >> 3) & 63;
        const int c = i & 7;
        const __half* src = t ? Vh : Kh;
        cpa16(st + t * ATT_KVB + SWZ((uint32_t)(r * 128 + c * 16)),
              src + tb + (size_t)(kv0 + r) * HDm + c * 8);
    }
}

__global__ __launch_bounds__(256, 2)
void attn_hmma(const __half* __restrict__ Qh_, const __half* __restrict__ Kh_,
               const __half* __restrict__ Vh_, __half* __restrict__ O)
{
    extern __shared__ __align__(1024) char smem[];
    const uint32_t sb = s2u(smem);
    const int tid = threadIdx.x, lane = tid & 31, warp = tid >> 5;
    const int bh = blockIdx.y;
    const int q0 = blockIdx.x * 128;
    const size_t tb = (size_t)bh * Sq * HDm;

    att_load_stage(sb + ATT_QB,           Kh_, Vh_, tb, 0,  tid); cpa_commit();
    att_load_stage(sb + ATT_QB + ATT_STG, Kh_, Vh_, tb, 64, tid); cpa_commit();
#pragma unroll
    for (int j = 0; j < 4; j++) {
        const int i = tid + j * 256;
        const int r = i >> 3, c = i & 7;
        cpa16(sb + SWZ((uint32_t)(r * 128 + c * 16)),
              Qh_ + tb + (size_t)(q0 + r) * HDm + c * 8);
    }
    cpa_commit();
    cpa_wait<0>();
    __syncthreads();

    uint32_t qf[4][4];
    {
        const uint32_t qrow = (uint32_t)((16*warp + (lane & 15)) * 128 + (lane >> 4) * 16);
#pragma unroll
        for (int kf = 0; kf < 4; kf++)
            ldsm4(qf[kf], sb + SWZ(qrow + kf * 32));
    }

    float acco[8][4];
#pragma unroll
    for (int nf = 0; nf < 8; nf++)
#pragma unroll
        for (int c = 0; c < 4; c++) acco[nf][c] = 0.f;
    float m0v = -1e30f, m1v = -1e30f, l0v = 0.f, l1v = 0.f;

    const int NT = Sq / 64;   // 32
    for (int c = 0; c < NT; c++) {
        if (c + 1 < NT) cpa_wait<1>(); else cpa_wait<0>();
        __syncthreads();
        if (c + 2 < NT) {
            att_load_stage(sb + ATT_QB + ((c + 2) % 3) * ATT_STG,
                           Kh_, Vh_, tb, (c + 2) * 64, tid);
            cpa_commit();
        }
        const uint32_t stb = sb + ATT_QB + (c % 3) * ATT_STG;

        float accs[8][4];
#pragma unroll
        for (int nf = 0; nf < 8; nf++)
#pragma unroll
            for (int q4 = 0; q4 < 4; q4++) accs[nf][q4] = 0.f;

#pragma unroll
        for (int kf = 0; kf < 4; kf++) {
            uint32_t bhf[4][4];
#pragma unroll
            for (int nfp = 0; nfp < 4; nfp++) {
                const uint32_t row = (uint32_t)(16*nfp + ((lane >> 4) << 3) + (lane & 7));
                const uint32_t kb  = (uint32_t)(kf * 32 + ((lane >> 3) & 1) * 16);
                ldsm4(bhf[nfp], stb + SWZ(row * 128 + kb));
            }
#pragma unroll
            for (int nfp = 0; nfp < 4; nfp++) {
                mma_f16(accs[2*nfp],   qf[kf], &bhf[nfp][0]);
                mma_f16(accs[2*nfp+1], qf[kf], &bhf[nfp][2]);
            }
        }

        // ---- online softmax, log2 domain, packed fp16 exp ----
        float mx0 = -1e30f, mx1 = -1e30f;
#pragma unroll
        for (int nf = 0; nf < 8; nf++) {
            mx0 = fmaxf(mx0, fmaxf(accs[nf][0], accs[nf][1]));
            mx1 = fmaxf(mx1, fmaxf(accs[nf][2], accs[nf][3]));
        }
#pragma unroll
        for (int off = 1; off <= 2; off <<= 1) {
            mx0 = fmaxf(mx0, __shfl_xor_sync(0xffffffffu, mx0, off));
            mx1 = fmaxf(mx1, __shfl_xor_sync(0xffffffffu, mx1, off));
        }
        const float mn0 = fmaxf(m0v, mx0), mn1 = fmaxf(m1v, mx1);
        const float cr0 = exp2f(m0v - mn0), cr1 = exp2f(m1v - mn1);
        uint32_t paccs[8][2];
        float sum0 = 0.f, sum1 = 0.f;
#pragma unroll
        for (int nf = 0; nf < 8; nf++) {
            const uint32_t p0 = h2exp2(accs[nf][0] - mn0, accs[nf][1] - mn0);
            const uint32_t p1 = h2exp2(accs[nf][2] - mn1, accs[nf][3] - mn1);
            paccs[nf][0] = p0; paccs[nf][1] = p1;
            float2 f0 = __half22float2(*(const __half2*)&p0);
            float2 f1 = __half22float2(*(const __half2*)&p1);
            sum0 += f0.x + f0.y;
            sum1 += f1.x + f1.y;
        }
#pragma unroll
        for (int off = 1; off <= 2; off <<= 1) {
            sum0 += __shfl_xor_sync(0xffffffffu, sum0, off);
            sum1 += __shfl_xor_sync(0xffffffffu, sum1, off);
        }
        l0v = l0v * cr0 + sum0;  m0v = mn0;
        l1v = l1v * cr1 + sum1;  m1v = mn1;
#pragma unroll
        for (int nf = 0; nf < 8; nf++) {
            acco[nf][0] *= cr0; acco[nf][1] *= cr0;
            acco[nf][2] *= cr1; acco[nf][3] *= cr1;
        }

        // ---- O += P V: P fragments are the packed exp outputs directly ----
#pragma unroll
        for (int kf2 = 0; kf2 < 4; kf2++) {
            uint32_t aP[4];
            aP[0] = paccs[2*kf2][0];
            aP[1] = paccs[2*kf2][1];
            aP[2] = paccs[2*kf2+1][0];
            aP[3] = paccs[2*kf2+1][1];
#pragma unroll
            for (int nfp2 = 0; nfp2 < 4; nfp2++) {
                const uint32_t row  = (uint32_t)(16*kf2 + ((lane >> 3) & 1) * 8 + (lane & 7));
                const uint32_t colb = (uint32_t)(nfp2 * 32 + (lane >> 4) * 16);
                uint32_t vhf[4];
                ldsm4t(vhf, stb + ATT_KVB + SWZ(row * 128 + colb));
                mma_f16(acco[2*nfp2],   aP, &vhf[0]);
                mma_f16(acco[2*nfp2+1], aP, &vhf[2]);
            }
        }
    }

    const float inv0 = 1.f / l0v, inv1 = 1.f / l1v;
    const int b = bh >> 4, h = bh & 15;
    const int s0 = q0 + warp * 16 + (lane >> 2), s1 = s0 + 8;
#pragma unroll
    for (int nf = 0; nf < 8; nf++) {
        const int col = h * HDm + nf * 8 + (lane & 3) * 2;
        const size_t o0 = (size_t)(b * Sq + s0) * Dm + col;
        const size_t o1 = (size_t)(b * Sq + s1) * Dm + col;
        *(uint32_t*)(O + o0) = pack_h2(acco[nf][0] * inv0, acco[nf][1] * inv0);
        *(uint32_t*)(O + o1) = pack_h2(acco[nf][2] * inv1, acco[nf][3] * inv1);
    }
}

// ---------------------------------------------------------------------------
extern "C" void kernel_launch(void* const* d_in, const int* in_sizes, int n_in,
                              void* d_out, int out_size)
{
    const float* x    = (const float*)d_in[0];
    const float* Wq   = (const float*)d_in[1];
    const float* bq   = (const float*)d_in[2];
    const float* Wk   = (const float*)d_in[3];
    const float* bk   = (const float*)d_in[4];
    const float* Wv   = (const float*)d_in[5];
    const float* bv   = (const float*)d_in[6];
    const float* Wo   = (const float*)d_in[7];
    const float* bo   = (const float*)d_in[8];
    const float* ln1g = (const float*)d_in[9];
    const float* ln1b = (const float*)d_in[10];
    const float* ln2g = (const float*)d_in[11];
    const float* ln2b = (const float*)d_in[12];
    const float* W1   = (const float*)d_in[13];
    const float* b1   = (const float*)d_in[14];
    const float* W2   = (const float*)d_in[15];
    const float* b2   = (const float*)d_in[16];
    float* out = (float*)d_out;

    float *x2, *bqkv;
    __half *a16, *h16, *q16, *k16, *v16;
    __half *wqkv, *wo, *w1, *w2;
    cudaGetSymbolAddress((void**)&x2,   g_x2);
    cudaGetSymbolAddress((void**)&bqkv, g_bqkv);
    cudaGetSymbolAddress((void**)&a16,  g_a);
    cudaGetSymbolAddress((void**)&h16,  g_h);
    cudaGetSymbolAddress((void**)&q16,  g_q);
    cudaGetSymbolAddress((void**)&k16,  g_k);
    cudaGetSymbolAddress((void**)&v16,  g_v);
    cudaGetSymbolAddress((void**)&wqkv, g_wqkv);
    cudaGetSymbolAddress((void**)&wo,   g_wo);
    cudaGetSymbolAddress((void**)&w1,   g_w1);
    cudaGetSymbolAddress((void**)&w2,   g_w2);

    cudaFuncSetAttribute(attn_hmma, cudaFuncAttributeMaxDynamicSharedMemorySize, ATT_SMEM);
    cudaFuncSetAttribute(gemm_hmma<1>, cudaFuncAttributeMaxDynamicSharedMemorySize, GEMM_SMEM);
    cudaFuncSetAttribute(gemm_hmma<2>, cudaFuncAttributeMaxDynamicSharedMemorySize, GEMM_SMEM);
    cudaFuncSetAttribute(gemm_hmma<3>, cudaFuncAttributeMaxDynamicSharedMemorySize, GEMM_SMEM);

    const dim3 blk(256);
    const dim3 wblk(32, 8);
    const dim3 gQKV(3*Dm / TNq, NTOK / TMq);  // (24, 64)
    const dim3 gP  (Dm   / TNq, NTOK / TMq);  // (8, 64)
    const dim3 gF1 (DFm  / TNq, NTOK / TMq);  // (32, 64)

    // 0) all weight converts + QKV bias concat in ONE launch
    wconv_all<<<12291, wblk>>>(Wq, Wk, Wv, Wo, W1, W2, bq, bk, bv,
                               wqkv, wo, w1, w2, bqkv);

    // 1) LN1 -> fp16
    ln_kernel<<<NTOK, blk>>>(x, ln1g, ln1b, a16);
    // 2) fused QKV projection -> fp16 scattered [B,H,S,64]; Q scaled 0.125*log2e
    gemm_hmma<3><<<gQKV, blk, GEMM_SMEM>>>(a16, wqkv, bqkv, nullptr, nullptr,
                                           q16, k16, v16, 3*Dm, Dm);
    // 3) attention (16q/warp, 2 CTAs/SM, f16x2 exp) -> fp16 [B,S,D]
    attn_hmma<<<dim3(Sq / 128, Bq * Hh), blk, ATT_SMEM>>>(q16, k16, v16, a16);
    // 4) output projection + residual -> x2 (f32)
    gemm_hmma<2><<<gP, blk, GEMM_SMEM>>>(a16, wo, bo, x, x2,
                                         nullptr, nullptr, nullptr, Dm, Dm);
    // 5) LN2 -> fp16
    ln_kernel<<<NTOK, blk>>>(x2, ln2g, ln2b, a16);
    // 6) FFN up + exact GELU -> fp16
    gemm_hmma<1><<<gF1, blk, GEMM_SMEM>>>(a16, w1, b1, nullptr, nullptr,
                                          h16, nullptr, nullptr, DFm, Dm);
    // 7) FFN down + residual -> out (f32)
    gemm_hmma<2><<<gP, blk, GEMM_SMEM>>>(h16, w2, b2, x2, out,
                                         nullptr, nullptr, nullptr, Dm, DFm);
}